// round 2
// baseline (speedup 1.0000x reference)
#include <cuda_runtime.h>
#include <math.h>

// ---------------------------------------------------------------------------
// MiniGPT forward, fp32. B=2 T=2048 D=256 H=4 DK=64 DFF=1024 L=4 V=32000
// kernel_launch contains ONLY kernel launches (graph-capture safe).
// ---------------------------------------------------------------------------

#define Tn   2048
#define Bn   2
#define Dn   256
#define Mrows 4096

// Scratch (static __device__ — no allocation allowed)
__device__ float g_x[Mrows * Dn];
__device__ float g_qkv[Mrows * 3 * Dn];
__device__ float g_att[Mrows * Dn];
__device__ float g_tmp[Mrows * Dn];
__device__ float g_h[Mrows * 1024];

// ---------------------------------------------------------------------------
// Embedding + sinusoidal positional encoding  (writes g_x)
// ---------------------------------------------------------------------------
__global__ void embed_pos_kernel(const int* __restrict__ tok,
                                 const float* __restrict__ emb)
{
    int row = blockIdx.x;          // 0..4095
    int d   = threadIdx.x;         // 0..255
    int t   = row & (Tn - 1);
    int token = tok[row];
    double div = exp(-(double)(d & ~1) * (9.210340371976184 / 256.0));
    double ang = (double)t * div;
    float  pe  = (d & 1) ? (float)cos(ang) : (float)sin(ang);
    g_x[row * Dn + d] = emb[token * Dn + d] + pe;
}

// ---------------------------------------------------------------------------
// NT GEMM body: C[4096,N] = A[4096,K] * W[N,K]^T + bias, optional relu.
// Tiles 128x128x8, 256 threads, 8x8 micro-tile per thread.
// ---------------------------------------------------------------------------
template<int N, int K, int RELU>
__device__ __forceinline__ void gemm_body(
    const float* __restrict__ A, const float* __restrict__ W,
    const float* __restrict__ bias, float* __restrict__ C)
{
    __shared__ float As[8][132];   // [k][m], padded
    __shared__ float Bs[8][132];   // [k][n]

    const int tid = threadIdx.x;
    const int tx  = tid & 15;
    const int ty  = tid >> 4;
    const int m0  = blockIdx.y << 7;
    const int n0  = blockIdx.x << 7;

    const int lm = tid >> 1;
    const int lk = (tid & 1) << 2;
    const float* Ap = A + (long)(m0 + lm) * K + lk;
    const float* Wp = W + (long)(n0 + lm) * K + lk;

    float acc[8][8];
#pragma unroll
    for (int i = 0; i < 8; i++)
#pragma unroll
        for (int j = 0; j < 8; j++) acc[i][j] = 0.f;

    for (int k0 = 0; k0 < K; k0 += 8) {
        float4 a4 = *(const float4*)(Ap + k0);
        float4 b4 = *(const float4*)(Wp + k0);
        As[lk + 0][lm] = a4.x; As[lk + 1][lm] = a4.y;
        As[lk + 2][lm] = a4.z; As[lk + 3][lm] = a4.w;
        Bs[lk + 0][lm] = b4.x; Bs[lk + 1][lm] = b4.y;
        Bs[lk + 2][lm] = b4.z; Bs[lk + 3][lm] = b4.w;
        __syncthreads();
#pragma unroll
        for (int k = 0; k < 8; k++) {
            float4 a0 = *(const float4*)&As[k][ty * 8];
            float4 a1 = *(const float4*)&As[k][ty * 8 + 4];
            float4 b0 = *(const float4*)&Bs[k][tx * 8];
            float4 b1 = *(const float4*)&Bs[k][tx * 8 + 4];
            float av[8] = {a0.x, a0.y, a0.z, a0.w, a1.x, a1.y, a1.z, a1.w};
            float bv[8] = {b0.x, b0.y, b0.z, b0.w, b1.x, b1.y, b1.z, b1.w};
#pragma unroll
            for (int i = 0; i < 8; i++)
#pragma unroll
                for (int j = 0; j < 8; j++)
                    acc[i][j] = fmaf(av[i], bv[j], acc[i][j]);
        }
        __syncthreads();
    }

    float4 bb0 = *(const float4*)(bias + n0 + tx * 8);
    float4 bb1 = *(const float4*)(bias + n0 + tx * 8 + 4);
    float bv[8] = {bb0.x, bb0.y, bb0.z, bb0.w, bb1.x, bb1.y, bb1.z, bb1.w};

#pragma unroll
    for (int i = 0; i < 8; i++) {
        float* cp = C + (long)(m0 + ty * 8 + i) * N + n0 + tx * 8;
        float r[8];
#pragma unroll
        for (int j = 0; j < 8; j++) {
            float v = acc[i][j] + bv[j];
            if (RELU) v = fmaxf(v, 0.f);
            r[j] = v;
        }
        *(float4*)(cp)     = make_float4(r[0], r[1], r[2], r[3]);
        *(float4*)(cp + 4) = make_float4(r[4], r[5], r[6], r[7]);
    }
}

// Thin wrappers binding scratch buffers by symbol (no host-side symbol lookup)
__global__ __launch_bounds__(256) void gemm_qkv(const float* W, const float* b)
{ gemm_body<768, 256, 0>(g_x, W, b, g_qkv); }

__global__ __launch_bounds__(256) void gemm_fc(const float* W, const float* b)
{ gemm_body<256, 256, 0>(g_att, W, b, g_tmp); }

__global__ __launch_bounds__(256) void gemm_w1(const float* W, const float* b)
{ gemm_body<1024, 256, 1>(g_x, W, b, g_h); }

__global__ __launch_bounds__(256) void gemm_w2(const float* W, const float* b)
{ gemm_body<256, 1024, 0>(g_h, W, b, g_tmp); }

__global__ __launch_bounds__(256) void gemm_logits(const float* W, const float* b,
                                                   float* out)
{ gemm_body<32000, 256, 0>(g_x, W, b, out); }

// ---------------------------------------------------------------------------
// Flash attention (causal), fp32. Block = (q_tile of 64, b*H+h). 256 threads.
// Static smem = 48KB exactly: Qs | KPs (K tile, then aliased by P tile) | Vs.
// Transposed tiles use XOR swizzle: col ^ ((row & 15) << 2)  (float4-safe).
// qkv layout [4096, 768]: cols [q: h*64 | k: 256+h*64 | v: 512+h*64].
// ---------------------------------------------------------------------------
#define SWZ(r, c) ((c) ^ (((r) & 15) << 2))

__global__ __launch_bounds__(256) void attn_kernel()
{
    __shared__ float Qs[4096];     // [d][m] transposed, pre-scaled
    __shared__ float KPs[4096];    // phase 1: K [d][n] transposed; phase 2: P [n][m]
    __shared__ float Vs[4096];     // [n][d]

    const int tid = threadIdx.x;
    const int tx  = tid & 15;
    const int ty  = tid >> 4;
    const int qt  = blockIdx.x;
    const int b   = blockIdx.y >> 2;
    const int h   = blockIdx.y & 3;
    const int q0  = qt << 6;
    const float* qbase = g_qkv + (long)b * Tn * 768 + h * 64;

    // Load Q tile (transposed, swizzled, scaled by 1/sqrt(64))
#pragma unroll
    for (int rep = 0; rep < 4; rep++) {
        int idx = tid + rep * 256;
        int rr  = idx >> 4;            // 0..63
        int d4  = (idx & 15) << 2;     // 0..60
        float4 q4 = *(const float4*)(qbase + (long)(q0 + rr) * 768 + d4);
        Qs[(d4 + 0) * 64 + SWZ(d4 + 0, rr)] = q4.x * 0.125f;
        Qs[(d4 + 1) * 64 + SWZ(d4 + 1, rr)] = q4.y * 0.125f;
        Qs[(d4 + 2) * 64 + SWZ(d4 + 2, rr)] = q4.z * 0.125f;
        Qs[(d4 + 3) * 64 + SWZ(d4 + 3, rr)] = q4.w * 0.125f;
    }

    float m_i[4], l_i[4], o[4][4];
#pragma unroll
    for (int i = 0; i < 4; i++) {
        m_i[i] = -1e30f; l_i[i] = 0.f;
#pragma unroll
        for (int j = 0; j < 4; j++) o[i][j] = 0.f;
    }

    for (int kt = 0; kt <= qt; kt++) {
        __syncthreads();               // prev iter done with KPs/Vs (& Q load visible)
        const int k0 = kt << 6;
#pragma unroll
        for (int rep = 0; rep < 4; rep++) {
            int idx = tid + rep * 256;
            int rr  = idx >> 4;
            int d4  = (idx & 15) << 2;
            const float* kb = qbase + (long)(k0 + rr) * 768;
            float4 k4 = *(const float4*)(kb + 256 + d4);
            KPs[(d4 + 0) * 64 + SWZ(d4 + 0, rr)] = k4.x;
            KPs[(d4 + 1) * 64 + SWZ(d4 + 1, rr)] = k4.y;
            KPs[(d4 + 2) * 64 + SWZ(d4 + 2, rr)] = k4.z;
            KPs[(d4 + 3) * 64 + SWZ(d4 + 3, rr)] = k4.w;
            float4 v4 = *(const float4*)(kb + 512 + d4);
            *(float4*)(Vs + rr * 64 + d4) = v4;
        }
        __syncthreads();

        // S = Q K^T (4x4 per thread)
        float s[4][4];
#pragma unroll
        for (int i = 0; i < 4; i++)
#pragma unroll
            for (int j = 0; j < 4; j++) s[i][j] = 0.f;
#pragma unroll 8
        for (int d = 0; d < 64; d++) {
            float4 qa = *(const float4*)&Qs[d * 64 + SWZ(d, ty * 4)];
            float4 ka = *(const float4*)&KPs[d * 64 + SWZ(d, tx * 4)];
            float qv[4] = {qa.x, qa.y, qa.z, qa.w};
            float kv[4] = {ka.x, ka.y, ka.z, ka.w};
#pragma unroll
            for (int i = 0; i < 4; i++)
#pragma unroll
                for (int j = 0; j < 4; j++)
                    s[i][j] = fmaf(qv[i], kv[j], s[i][j]);
        }

        if (kt == qt) {                // diagonal tile: causal mask (local coords)
#pragma unroll
            for (int i = 0; i < 4; i++)
#pragma unroll
                for (int j = 0; j < 4; j++)
                    if (tx * 4 + j > ty * 4 + i) s[i][j] = -1e30f;
        }

        // Online softmax per row (row group = 16 consecutive lanes, same ty)
#pragma unroll
        for (int i = 0; i < 4; i++) {
            float mx = fmaxf(fmaxf(s[i][0], s[i][1]), fmaxf(s[i][2], s[i][3]));
#pragma unroll
            for (int ofs = 8; ofs; ofs >>= 1)
                mx = fmaxf(mx, __shfl_xor_sync(0xffffffffu, mx, ofs, 16));
            float mn   = fmaxf(m_i[i], mx);
            float corr = expf(m_i[i] - mn);
            float rs = 0.f;
#pragma unroll
            for (int j = 0; j < 4; j++) {
                s[i][j] = expf(s[i][j] - mn);
                rs += s[i][j];
            }
#pragma unroll
            for (int ofs = 8; ofs; ofs >>= 1)
                rs += __shfl_xor_sync(0xffffffffu, rs, ofs, 16);
            l_i[i] = l_i[i] * corr + rs;
            m_i[i] = mn;
#pragma unroll
            for (int j = 0; j < 4; j++) o[i][j] *= corr;
        }

        __syncthreads();               // everyone done READING K tile
        // Store P transposed [n][m] into the K buffer (swizzled)
#pragma unroll
        for (int i = 0; i < 4; i++)
#pragma unroll
            for (int j = 0; j < 4; j++) {
                int n = tx * 4 + j;
                KPs[n * 64 + SWZ(n, ty * 4 + i)] = s[i][j];
            }
        __syncthreads();

        // O += P V
#pragma unroll 8
        for (int n = 0; n < 64; n++) {
            float4 p4 = *(const float4*)&KPs[n * 64 + SWZ(n, ty * 4)];
            float4 v4 = *(const float4*)&Vs[n * 64 + tx * 4];
            float pv[4] = {p4.x, p4.y, p4.z, p4.w};
            float vv[4] = {v4.x, v4.y, v4.z, v4.w};
#pragma unroll
            for (int i = 0; i < 4; i++)
#pragma unroll
                for (int j = 0; j < 4; j++)
                    o[i][j] = fmaf(pv[i], vv[j], o[i][j]);
        }
    }

    // Write O (normalized) to g_att
#pragma unroll
    for (int i = 0; i < 4; i++) {
        float inv = 1.f / l_i[i];
        float4 r = make_float4(o[i][0] * inv, o[i][1] * inv,
                               o[i][2] * inv, o[i][3] * inv);
        *(float4*)(g_att + (long)(b * Tn + q0 + ty * 4 + i) * Dn + h * 64 + tx * 4) = r;
    }
}

// ---------------------------------------------------------------------------
// LayerNorm bodies: x = LN(x [+ g_tmp]) * sc + bi. One warp per 256-wide row.
// ---------------------------------------------------------------------------
template<int ADD>
__device__ __forceinline__ void ln_body(const float* __restrict__ sc,
                                        const float* __restrict__ bi)
{
    int row  = blockIdx.x * 8 + (threadIdx.x >> 5);
    int lane = threadIdx.x & 31;
    const float* pa = g_x + (long)row * Dn + lane * 8;
    float v[8];
    {
        float4 v0 = *(const float4*)pa;
        float4 v1 = *(const float4*)(pa + 4);
        v[0] = v0.x; v[1] = v0.y; v[2] = v0.z; v[3] = v0.w;
        v[4] = v1.x; v[5] = v1.y; v[6] = v1.z; v[7] = v1.w;
    }
    if (ADD) {
        const float* pr = g_tmp + (long)row * Dn + lane * 8;
        float4 r0 = *(const float4*)pr;
        float4 r1 = *(const float4*)(pr + 4);
        v[0] += r0.x; v[1] += r0.y; v[2] += r0.z; v[3] += r0.w;
        v[4] += r1.x; v[5] += r1.y; v[6] += r1.z; v[7] += r1.w;
    }
    float s = 0.f;
#pragma unroll
    for (int k = 0; k < 8; k++) s += v[k];
#pragma unroll
    for (int ofs = 16; ofs; ofs >>= 1) s += __shfl_xor_sync(0xffffffffu, s, ofs);
    float mu = s * (1.f / 256.f);
    float var = 0.f;
#pragma unroll
    for (int k = 0; k < 8; k++) { float d = v[k] - mu; var = fmaf(d, d, var); }
#pragma unroll
    for (int ofs = 16; ofs; ofs >>= 1) var += __shfl_xor_sync(0xffffffffu, var, ofs);
    float rstd = rsqrtf(var * (1.f / 256.f) + 1e-5f);

    float4 s0 = *(const float4*)(sc + lane * 8);
    float4 s1 = *(const float4*)(sc + lane * 8 + 4);
    float4 b0 = *(const float4*)(bi + lane * 8);
    float4 b1 = *(const float4*)(bi + lane * 8 + 4);
    float scv[8] = {s0.x, s0.y, s0.z, s0.w, s1.x, s1.y, s1.z, s1.w};
    float biv[8] = {b0.x, b0.y, b0.z, b0.w, b1.x, b1.y, b1.z, b1.w};
    float o[8];
#pragma unroll
    for (int k = 0; k < 8; k++) o[k] = fmaf((v[k] - mu) * rstd, scv[k], biv[k]);
    float* po = g_x + (long)row * Dn + lane * 8;
    *(float4*)po       = make_float4(o[0], o[1], o[2], o[3]);
    *(float4*)(po + 4) = make_float4(o[4], o[5], o[6], o[7]);
}

__global__ void add_ln_kernel(const float* sc, const float* bi) { ln_body<1>(sc, bi); }
__global__ void final_ln_kernel(const float* sc, const float* bi) { ln_body<0>(sc, bi); }

// ---------------------------------------------------------------------------
// Orchestration: kernel launches ONLY.
// ---------------------------------------------------------------------------
extern "C" void kernel_launch(void* const* d_in, const int* in_sizes, int n_in,
                              void* d_out, int out_size)
{
    const int*   tokens = (const int*)d_in[0];
    const float* embedw = (const float*)d_in[1];
    const float* qkv_w  = (const float*)d_in[2];
    const float* qkv_b  = (const float*)d_in[3];
    const float* fc_w   = (const float*)d_in[4];
    const float* fc_b   = (const float*)d_in[5];
    const float* ln1_s  = (const float*)d_in[6];
    const float* ln1_b  = (const float*)d_in[7];
    const float* w1     = (const float*)d_in[8];
    const float* b1     = (const float*)d_in[9];
    const float* w2     = (const float*)d_in[10];
    const float* b2     = (const float*)d_in[11];
    const float* ln2_s  = (const float*)d_in[12];
    const float* ln2_b  = (const float*)d_in[13];
    const float* lnf_s  = (const float*)d_in[14];
    const float* lnf_b  = (const float*)d_in[15];
    const float* out_w  = (const float*)d_in[16];
    const float* out_b  = (const float*)d_in[17];
    float* logits = (float*)d_out;

    embed_pos_kernel<<<Mrows, Dn>>>(tokens, embedw);

    for (int l = 0; l < 4; l++) {
        gemm_qkv<<<dim3(6, 32), 256>>>(qkv_w + (long)l * 768 * 256, qkv_b + l * 768);
        attn_kernel<<<dim3(Tn / 64, Bn * 4), 256>>>();
        gemm_fc<<<dim3(2, 32), 256>>>(fc_w + (long)l * 256 * 256, fc_b + l * 256);
        add_ln_kernel<<<Mrows / 8, 256>>>(ln1_s + l * 256, ln1_b + l * 256);
        gemm_w1<<<dim3(8, 32), 256>>>(w1 + (long)l * 1024 * 256, b1 + l * 1024);
        gemm_w2<<<dim3(2, 32), 256>>>(w2 + (long)l * 256 * 1024, b2 + l * 256);
        add_ln_kernel<<<Mrows / 8, 256>>>(ln2_s + l * 256, ln2_b + l * 256);
    }
    final_ln_kernel<<<Mrows / 8, 256>>>(lnf_s, lnf_b);
    gemm_logits<<<dim3(32000 / 128, 32), 256>>>(out_w, out_b, logits);
}

// round 4
// speedup vs baseline: 1.4248x; 1.4248x over previous
#include <cuda_runtime.h>
#include <cuda_bf16.h>
#include <math.h>
#include <stdint.h>

// ---------------------------------------------------------------------------
// MiniGPT forward. B=2 T=2048 D=256 H=4 DK=64 DFF=1024 L=4 V=32000
// GEMMs: mma.sync bf16x3 (fp32 -> bf16 hi/lo split, 3-term compensated HMMA).
// Attention: fp32 flash (48KB static smem). LN/embed: fp32.
// NOTE: tcgen05 is NOT available (harness PTX target is compute_103, no 'a').
// ---------------------------------------------------------------------------

#define Tn    2048
#define Bn    2
#define Dn    256
#define Mrows 4096

// ------------------------- fp32 scratch ------------------------------------
__device__ float g_x[Mrows * Dn];
__device__ float g_qkv[Mrows * 3 * Dn];
__device__ float g_att[Mrows * Dn];
__device__ float g_tmp[Mrows * Dn];
__device__ float g_h[Mrows * 1024];

// ------------------------- bf16 hi/lo scratch ------------------------------
__device__ __nv_bfloat16 g_acth[Mrows * 1024];
__device__ __nv_bfloat16 g_actl[Mrows * 1024];
__device__ __nv_bfloat16 g_wqkv_h[4 * 768 * 256],  g_wqkv_l[4 * 768 * 256];
__device__ __nv_bfloat16 g_wfc_h [4 * 256 * 256],  g_wfc_l [4 * 256 * 256];
__device__ __nv_bfloat16 g_w1_h  [4 * 1024 * 256], g_w1_l  [4 * 1024 * 256];
__device__ __nv_bfloat16 g_w2_h  [4 * 256 * 1024], g_w2_l  [4 * 256 * 1024];
__device__ __nv_bfloat16 g_wout_h[32000 * 256],    g_wout_l[32000 * 256];

// ---------------------------------------------------------------------------
// PTX helpers (baseline sm_80-class instructions only)
// ---------------------------------------------------------------------------
__device__ __forceinline__ uint32_t smem_to_u32(const void* p) {
    uint32_t a;
    asm("{ .reg .u64 t; cvta.to.shared.u64 t, %1; cvt.u32.u64 %0, t; }"
        : "=r"(a) : "l"(p));
    return a;
}
__device__ __forceinline__ void ldsm4(uint32_t* r, uint32_t addr) {
    asm volatile("ldmatrix.sync.aligned.m8n8.x4.shared.b16 {%0,%1,%2,%3}, [%4];"
                 : "=r"(r[0]), "=r"(r[1]), "=r"(r[2]), "=r"(r[3]) : "r"(addr));
}
__device__ __forceinline__ void mma16816(float* d, const uint32_t* a,
                                         uint32_t b0, uint32_t b1) {
    asm volatile(
        "mma.sync.aligned.m16n8k16.row.col.f32.bf16.bf16.f32 "
        "{%0,%1,%2,%3}, {%4,%5,%6,%7}, {%8,%9}, {%0,%1,%2,%3};"
        : "+f"(d[0]), "+f"(d[1]), "+f"(d[2]), "+f"(d[3])
        : "r"(a[0]), "r"(a[1]), "r"(a[2]), "r"(a[3]), "r"(b0), "r"(b1));
}
#define CP_ASYNC16(dst, src) \
    asm volatile("cp.async.cg.shared.global [%0], [%1], 16;" \
                 :: "r"(dst), "l"(src) : "memory")
#define CP_COMMIT()  asm volatile("cp.async.commit_group;" ::: "memory")
#define CP_WAIT0()   asm volatile("cp.async.wait_group 0;" ::: "memory")

// ---------------------------------------------------------------------------
// fp32 -> bf16 hi/lo split
// ---------------------------------------------------------------------------
__device__ __forceinline__ void split_body(const float* __restrict__ s,
                                           __nv_bfloat16* __restrict__ h,
                                           __nv_bfloat16* __restrict__ l, int n)
{
    int i = blockIdx.x * blockDim.x + threadIdx.x;
    int stride = gridDim.x * blockDim.x;
    for (int idx = i; idx < n / 4; idx += stride) {
        float4 v = ((const float4*)s)[idx];
        __nv_bfloat16 h0 = __float2bfloat16(v.x);
        __nv_bfloat16 h1 = __float2bfloat16(v.y);
        __nv_bfloat16 h2 = __float2bfloat16(v.z);
        __nv_bfloat16 h3 = __float2bfloat16(v.w);
        __nv_bfloat16 l0 = __float2bfloat16(v.x - __bfloat162float(h0));
        __nv_bfloat16 l1 = __float2bfloat16(v.y - __bfloat162float(h1));
        __nv_bfloat16 l2 = __float2bfloat16(v.z - __bfloat162float(h2));
        __nv_bfloat16 l3 = __float2bfloat16(v.w - __bfloat162float(h3));
        ((__nv_bfloat162*)h)[idx * 2 + 0] = __nv_bfloat162(h0, h1);
        ((__nv_bfloat162*)h)[idx * 2 + 1] = __nv_bfloat162(h2, h3);
        ((__nv_bfloat162*)l)[idx * 2 + 0] = __nv_bfloat162(l0, l1);
        ((__nv_bfloat162*)l)[idx * 2 + 1] = __nv_bfloat162(l2, l3);
    }
}
__global__ void split_wqkv(const float* s) { split_body(s, g_wqkv_h, g_wqkv_l, 4*768*256); }
__global__ void split_wfc (const float* s) { split_body(s, g_wfc_h,  g_wfc_l,  4*256*256); }
__global__ void split_w1k (const float* s) { split_body(s, g_w1_h,   g_w1_l,   4*1024*256); }
__global__ void split_w2k (const float* s) { split_body(s, g_w2_h,   g_w2_l,   4*256*1024); }
__global__ void split_wout(const float* s) { split_body(s, g_wout_h, g_wout_l, 32000*256); }
__global__ void split_ax () { split_body(g_x,   g_acth, g_actl, Mrows*256); }
__global__ void split_aat() { split_body(g_att, g_acth, g_actl, Mrows*256); }
__global__ void split_ah () { split_body(g_h,   g_acth, g_actl, Mrows*1024); }

// ---------------------------------------------------------------------------
// mma.sync bf16x3 GEMM: C[4096,N] = A*W^T + bias (A,W split hi/lo bf16).
// CTA 128x128, 512 threads (16 warps, 4x4 grid, 32x32 per warp).
// K staged 64 wide: 4 tiles (Ah,Al,Bh,Bl) 128x64 bf16, 128B rows, SW128
// XOR swizzle; double buffered => 128KB dynamic smem, cp.async pipeline.
// ---------------------------------------------------------------------------
#define GSMEM (2 * 65536)

template<int N, int K, int RELU>
__device__ __forceinline__ void gemm_tc_body(
    const __nv_bfloat16* __restrict__ Ah, const __nv_bfloat16* __restrict__ Al,
    const __nv_bfloat16* __restrict__ Bh, const __nv_bfloat16* __restrict__ Bl,
    const float* __restrict__ bias, float* __restrict__ C)
{
    extern __shared__ char smem[];
    const uint32_t sb = smem_to_u32(smem);
    const int tid  = threadIdx.x;
    const int wid  = tid >> 5;
    const int lane = tid & 31;
    const int m0   = blockIdx.y << 7;
    const int n0   = blockIdx.x << 7;
    constexpr int NST = K / 64;
    const int wr = wid & 3;        // m: wr*32
    const int wc = wid >> 2;       // n: wc*32

    // ---- loader mapping: thread -> (tile lt, row lr), 128B per stage -------
    const int lr = tid & 127;
    const int lt = tid >> 7;
    const __nv_bfloat16* gptr =
        (lt == 0) ? Ah + (long)(m0 + lr) * K :
        (lt == 1) ? Al + (long)(m0 + lr) * K :
        (lt == 2) ? Bh + (long)(n0 + lr) * K :
                    Bl + (long)(n0 + lr) * K;
    const uint32_t dstbase = sb + lt * 16384 + lr * 128;
    const uint32_t swrow   = (uint32_t)((lr & 7) << 4);

    // prologue: stage 0 loads
    {
        const char* src = (const char*)gptr;
#pragma unroll
        for (int c = 0; c < 8; c++)
            CP_ASYNC16(dstbase + ((c * 16) ^ swrow), src + c * 16);
        CP_COMMIT();
    }

    float acc[2][4][4];
#pragma unroll
    for (int i = 0; i < 2; i++)
#pragma unroll
        for (int j = 0; j < 4; j++)
#pragma unroll
            for (int q = 0; q < 4; q++) acc[i][j][q] = 0.f;

    for (int s = 0; s < NST; s++) {
        CP_WAIT0();
        __syncthreads();           // stage s visible; prev buffer free
        if (s + 1 < NST) {
            const uint32_t db = dstbase + (uint32_t)(((s + 1) & 1) * 65536);
            const char* src = (const char*)(gptr + (s + 1) * 64);
#pragma unroll
            for (int c = 0; c < 8; c++)
                CP_ASYNC16(db + ((c * 16) ^ swrow), src + c * 16);
            CP_COMMIT();
        }
        const uint32_t bufb = sb + (uint32_t)((s & 1) * 65536);

#pragma unroll
        for (int ko = 0; ko < 64; ko += 16) {
            uint32_t afr[2][2][4];
            uint32_t bfr[2][2][4];
            {
                const int rowb = wr * 32 + (lane & 15);
                const int cb   = ko * 2 + ((lane >> 4) << 4);
#pragma unroll
                for (int t = 0; t < 2; t++)
#pragma unroll
                    for (int mi = 0; mi < 2; mi++) {
                        int row = rowb + mi * 16;
                        uint32_t addr = bufb + t * 16384 + row * 128
                                      + (uint32_t)(cb ^ ((row & 7) << 4));
                        ldsm4(afr[t][mi], addr);
                    }
            }
            {
                const int rowb = wc * 32 + (lane & 7) + ((lane >> 4) << 3);
                const int cb   = ko * 2 + (((lane >> 3) & 1) << 4);
#pragma unroll
                for (int t = 0; t < 2; t++)
#pragma unroll
                    for (int nj = 0; nj < 2; nj++) {
                        int row = rowb + nj * 16;
                        uint32_t addr = bufb + 32768 + t * 16384 + row * 128
                                      + (uint32_t)(cb ^ ((row & 7) << 4));
                        ldsm4(bfr[t][nj], addr);
                    }
            }
#pragma unroll
            for (int mi = 0; mi < 2; mi++)
#pragma unroll
                for (int nj = 0; nj < 2; nj++)
#pragma unroll
                    for (int hh = 0; hh < 2; hh++) {
                        const int nc = nj * 2 + hh;
                        const uint32_t bh0 = bfr[0][nj][hh * 2];
                        const uint32_t bh1 = bfr[0][nj][hh * 2 + 1];
                        const uint32_t bl0 = bfr[1][nj][hh * 2];
                        const uint32_t bl1 = bfr[1][nj][hh * 2 + 1];
                        mma16816(acc[mi][nc], afr[0][mi], bh0, bh1);  // AhBh
                        mma16816(acc[mi][nc], afr[0][mi], bl0, bl1);  // AhBl
                        mma16816(acc[mi][nc], afr[1][mi], bh0, bh1);  // AlBh
                    }
        }
        __syncthreads();           // done reading buf s before it's refilled
    }

    // ---- epilogue: regs -> C with bias (+relu) -----------------------------
#pragma unroll
    for (int mi = 0; mi < 2; mi++)
#pragma unroll
        for (int nc = 0; nc < 4; nc++) {
            int row = m0 + wr * 32 + mi * 16 + (lane >> 2);
            int col = n0 + wc * 32 + nc * 8 + (lane & 3) * 2;
            float b0v = bias[col], b1v = bias[col + 1];
            float v0 = acc[mi][nc][0] + b0v;
            float v1 = acc[mi][nc][1] + b1v;
            float v2 = acc[mi][nc][2] + b0v;
            float v3 = acc[mi][nc][3] + b1v;
            if (RELU) {
                v0 = fmaxf(v0, 0.f); v1 = fmaxf(v1, 0.f);
                v2 = fmaxf(v2, 0.f); v3 = fmaxf(v3, 0.f);
            }
            *(float2*)(C + (long)row * N + col)       = make_float2(v0, v1);
            *(float2*)(C + (long)(row + 8) * N + col) = make_float2(v2, v3);
        }
}

__global__ __launch_bounds__(512) void gemm_qkv_tc(int l, const float* bias)
{ gemm_tc_body<768, 256, 0>(g_acth, g_actl, g_wqkv_h + l*196608, g_wqkv_l + l*196608, bias, g_qkv); }
__global__ __launch_bounds__(512) void gemm_fc_tc(int l, const float* bias)
{ gemm_tc_body<256, 256, 0>(g_acth, g_actl, g_wfc_h + l*65536, g_wfc_l + l*65536, bias, g_tmp); }
__global__ __launch_bounds__(512) void gemm_w1_tc(int l, const float* bias)
{ gemm_tc_body<1024, 256, 1>(g_acth, g_actl, g_w1_h + l*262144, g_w1_l + l*262144, bias, g_h); }
__global__ __launch_bounds__(512) void gemm_w2_tc(int l, const float* bias)
{ gemm_tc_body<256, 1024, 0>(g_acth, g_actl, g_w2_h + l*262144, g_w2_l + l*262144, bias, g_tmp); }
__global__ __launch_bounds__(512) void gemm_logits_tc(const float* bias, float* out)
{ gemm_tc_body<32000, 256, 0>(g_acth, g_actl, g_wout_h, g_wout_l, bias, out); }

// ---------------------------------------------------------------------------
// Embedding + positional encoding
// ---------------------------------------------------------------------------
__global__ void embed_pos_kernel(const int* __restrict__ tok,
                                 const float* __restrict__ emb)
{
    int row = blockIdx.x;
    int d   = threadIdx.x;
    int t   = row & (Tn - 1);
    int token = tok[row];
    double div = exp(-(double)(d & ~1) * (9.210340371976184 / 256.0));
    double ang = (double)t * div;
    float  pe  = (d & 1) ? (float)cos(ang) : (float)sin(ang);
    g_x[row * Dn + d] = emb[token * Dn + d] + pe;
}

// ---------------------------------------------------------------------------
// Flash attention (causal), fp32, 48KB static smem
// ---------------------------------------------------------------------------
#define SWZ(r, c) ((c) ^ (((r) & 15) << 2))

__global__ __launch_bounds__(256) void attn_kernel()
{
    __shared__ float Qs[4096];
    __shared__ float KPs[4096];
    __shared__ float Vs[4096];

    const int tid = threadIdx.x;
    const int tx  = tid & 15;
    const int ty  = tid >> 4;
    const int qt  = blockIdx.x;
    const int b   = blockIdx.y >> 2;
    const int h   = blockIdx.y & 3;
    const int q0  = qt << 6;
    const float* qbase = g_qkv + (long)b * Tn * 768 + h * 64;

#pragma unroll
    for (int rep = 0; rep < 4; rep++) {
        int idx = tid + rep * 256;
        int rr  = idx >> 4;
        int d4  = (idx & 15) << 2;
        float4 q4 = *(const float4*)(qbase + (long)(q0 + rr) * 768 + d4);
        Qs[(d4 + 0) * 64 + SWZ(d4 + 0, rr)] = q4.x * 0.125f;
        Qs[(d4 + 1) * 64 + SWZ(d4 + 1, rr)] = q4.y * 0.125f;
        Qs[(d4 + 2) * 64 + SWZ(d4 + 2, rr)] = q4.z * 0.125f;
        Qs[(d4 + 3) * 64 + SWZ(d4 + 3, rr)] = q4.w * 0.125f;
    }

    float m_i[4], l_i[4], o[4][4];
#pragma unroll
    for (int i = 0; i < 4; i++) {
        m_i[i] = -1e30f; l_i[i] = 0.f;
#pragma unroll
        for (int j = 0; j < 4; j++) o[i][j] = 0.f;
    }

    for (int kt = 0; kt <= qt; kt++) {
        __syncthreads();
        const int k0 = kt << 6;
#pragma unroll
        for (int rep = 0; rep < 4; rep++) {
            int idx = tid + rep * 256;
            int rr  = idx >> 4;
            int d4  = (idx & 15) << 2;
            const float* kb = qbase + (long)(k0 + rr) * 768;
            float4 k4 = *(const float4*)(kb + 256 + d4);
            KPs[(d4 + 0) * 64 + SWZ(d4 + 0, rr)] = k4.x;
            KPs[(d4 + 1) * 64 + SWZ(d4 + 1, rr)] = k4.y;
            KPs[(d4 + 2) * 64 + SWZ(d4 + 2, rr)] = k4.z;
            KPs[(d4 + 3) * 64 + SWZ(d4 + 3, rr)] = k4.w;
            float4 v4 = *(const float4*)(kb + 512 + d4);
            *(float4*)(Vs + rr * 64 + d4) = v4;
        }
        __syncthreads();

        float s[4][4];
#pragma unroll
        for (int i = 0; i < 4; i++)
#pragma unroll
            for (int j = 0; j < 4; j++) s[i][j] = 0.f;
#pragma unroll 8
        for (int d = 0; d < 64; d++) {
            float4 qa = *(const float4*)&Qs[d * 64 + SWZ(d, ty * 4)];
            float4 ka = *(const float4*)&KPs[d * 64 + SWZ(d, tx * 4)];
            float qv[4] = {qa.x, qa.y, qa.z, qa.w};
            float kv[4] = {ka.x, ka.y, ka.z, ka.w};
#pragma unroll
            for (int i = 0; i < 4; i++)
#pragma unroll
                for (int j = 0; j < 4; j++)
                    s[i][j] = fmaf(qv[i], kv[j], s[i][j]);
        }

        if (kt == qt) {
#pragma unroll
            for (int i = 0; i < 4; i++)
#pragma unroll
                for (int j = 0; j < 4; j++)
                    if (tx * 4 + j > ty * 4 + i) s[i][j] = -1e30f;
        }

#pragma unroll
        for (int i = 0; i < 4; i++) {
            float mx = fmaxf(fmaxf(s[i][0], s[i][1]), fmaxf(s[i][2], s[i][3]));
#pragma unroll
            for (int ofs = 8; ofs; ofs >>= 1)
                mx = fmaxf(mx, __shfl_xor_sync(0xffffffffu, mx, ofs, 16));
            float mn   = fmaxf(m_i[i], mx);
            float corr = expf(m_i[i] - mn);
            float rs = 0.f;
#pragma unroll
            for (int j = 0; j < 4; j++) {
                s[i][j] = expf(s[i][j] - mn);
                rs += s[i][j];
            }
#pragma unroll
            for (int ofs = 8; ofs; ofs >>= 1)
                rs += __shfl_xor_sync(0xffffffffu, rs, ofs, 16);
            l_i[i] = l_i[i] * corr + rs;
            m_i[i] = mn;
#pragma unroll
            for (int j = 0; j < 4; j++) o[i][j] *= corr;
        }

        __syncthreads();
#pragma unroll
        for (int i = 0; i < 4; i++)
#pragma unroll
            for (int j = 0; j < 4; j++) {
                int n = tx * 4 + j;
                KPs[n * 64 + SWZ(n, ty * 4 + i)] = s[i][j];
            }
        __syncthreads();

#pragma unroll 8
        for (int n = 0; n < 64; n++) {
            float4 p4 = *(const float4*)&KPs[n * 64 + SWZ(n, ty * 4)];
            float4 v4 = *(const float4*)&Vs[n * 64 + tx * 4];
            float pv[4] = {p4.x, p4.y, p4.z, p4.w};
            float vv[4] = {v4.x, v4.y, v4.z, v4.w};
#pragma unroll
            for (int i = 0; i < 4; i++)
#pragma unroll
                for (int j = 0; j < 4; j++)
                    o[i][j] = fmaf(pv[i], vv[j], o[i][j]);
        }
    }

#pragma unroll
    for (int i = 0; i < 4; i++) {
        float inv = 1.f / l_i[i];
        float4 rr = make_float4(o[i][0] * inv, o[i][1] * inv,
                                o[i][2] * inv, o[i][3] * inv);
        *(float4*)(g_att + (long)(b * Tn + q0 + ty * 4 + i) * Dn + h * 64 + tx * 4) = rr;
    }
}

// ---------------------------------------------------------------------------
// LayerNorm: x = LN(x [+ g_tmp]) * sc + bi
// ---------------------------------------------------------------------------
template<int ADD>
__device__ __forceinline__ void ln_body(const float* __restrict__ sc,
                                        const float* __restrict__ bi)
{
    int row  = blockIdx.x * 8 + (threadIdx.x >> 5);
    int lane = threadIdx.x & 31;
    const float* pa = g_x + (long)row * Dn + lane * 8;
    float v[8];
    {
        float4 v0 = *(const float4*)pa;
        float4 v1 = *(const float4*)(pa + 4);
        v[0] = v0.x; v[1] = v0.y; v[2] = v0.z; v[3] = v0.w;
        v[4] = v1.x; v[5] = v1.y; v[6] = v1.z; v[7] = v1.w;
    }
    if (ADD) {
        const float* pr = g_tmp + (long)row * Dn + lane * 8;
        float4 r0 = *(const float4*)pr;
        float4 r1 = *(const float4*)(pr + 4);
        v[0] += r0.x; v[1] += r0.y; v[2] += r0.z; v[3] += r0.w;
        v[4] += r1.x; v[5] += r1.y; v[6] += r1.z; v[7] += r1.w;
    }
    float s = 0.f;
#pragma unroll
    for (int k = 0; k < 8; k++) s += v[k];
#pragma unroll
    for (int ofs = 16; ofs; ofs >>= 1) s += __shfl_xor_sync(0xffffffffu, s, ofs);
    float mu = s * (1.f / 256.f);
    float var = 0.f;
#pragma unroll
    for (int k = 0; k < 8; k++) { float d = v[k] - mu; var = fmaf(d, d, var); }
#pragma unroll
    for (int ofs = 16; ofs; ofs >>= 1) var += __shfl_xor_sync(0xffffffffu, var, ofs);
    float rstd = rsqrtf(var * (1.f / 256.f) + 1e-5f);

    float4 s0 = *(const float4*)(sc + lane * 8);
    float4 s1 = *(const float4*)(sc + lane * 8 + 4);
    float4 b0 = *(const float4*)(bi + lane * 8);
    float4 b1 = *(const float4*)(bi + lane * 8 + 4);
    float scv[8] = {s0.x, s0.y, s0.z, s0.w, s1.x, s1.y, s1.z, s1.w};
    float biv[8] = {b0.x, b0.y, b0.z, b0.w, b1.x, b1.y, b1.z, b1.w};
    float o[8];
#pragma unroll
    for (int k = 0; k < 8; k++) o[k] = fmaf((v[k] - mu) * rstd, scv[k], biv[k]);
    float* po = g_x + (long)row * Dn + lane * 8;
    *(float4*)po       = make_float4(o[0], o[1], o[2], o[3]);
    *(float4*)(po + 4) = make_float4(o[4], o[5], o[6], o[7]);
}
__global__ void add_ln_kernel(const float* sc, const float* bi) { ln_body<1>(sc, bi); }
__global__ void final_ln_kernel(const float* sc, const float* bi) { ln_body<0>(sc, bi); }

// ---------------------------------------------------------------------------
// Orchestration
// ---------------------------------------------------------------------------
extern "C" void kernel_launch(void* const* d_in, const int* in_sizes, int n_in,
                              void* d_out, int out_size)
{
    const int*   tokens = (const int*)d_in[0];
    const float* embedw = (const float*)d_in[1];
    const float* qkv_w  = (const float*)d_in[2];
    const float* qkv_b  = (const float*)d_in[3];
    const float* fc_w   = (const float*)d_in[4];
    const float* fc_b   = (const float*)d_in[5];
    const float* ln1_s  = (const float*)d_in[6];
    const float* ln1_b  = (const float*)d_in[7];
    const float* w1     = (const float*)d_in[8];
    const float* b1     = (const float*)d_in[9];
    const float* w2     = (const float*)d_in[10];
    const float* b2     = (const float*)d_in[11];
    const float* ln2_s  = (const float*)d_in[12];
    const float* ln2_b  = (const float*)d_in[13];
    const float* lnf_s  = (const float*)d_in[14];
    const float* lnf_b  = (const float*)d_in[15];
    const float* out_w  = (const float*)d_in[16];
    const float* out_b  = (const float*)d_in[17];
    float* logits = (float*)d_out;

    static bool attr_done = false;
    if (!attr_done) {
        cudaFuncSetAttribute((const void*)gemm_qkv_tc,
            cudaFuncAttributeMaxDynamicSharedMemorySize, GSMEM);
        cudaFuncSetAttribute((const void*)gemm_fc_tc,
            cudaFuncAttributeMaxDynamicSharedMemorySize, GSMEM);
        cudaFuncSetAttribute((const void*)gemm_w1_tc,
            cudaFuncAttributeMaxDynamicSharedMemorySize, GSMEM);
        cudaFuncSetAttribute((const void*)gemm_w2_tc,
            cudaFuncAttributeMaxDynamicSharedMemorySize, GSMEM);
        cudaFuncSetAttribute((const void*)gemm_logits_tc,
            cudaFuncAttributeMaxDynamicSharedMemorySize, GSMEM);
        attr_done = true;
    }

    // weight splits (deterministic each launch)
    split_wqkv<<<512, 256>>>(qkv_w);
    split_wfc <<<512, 256>>>(fc_w);
    split_w1k <<<512, 256>>>(w1);
    split_w2k <<<512, 256>>>(w2);
    split_wout<<<2048, 256>>>(out_w);

    embed_pos_kernel<<<Mrows, Dn>>>(tokens, embedw);

    for (int l = 0; l < 4; l++) {
        split_ax<<<512, 256>>>();
        gemm_qkv_tc<<<dim3(6, 32), 512, GSMEM>>>(l, qkv_b + l * 768);
        attn_kernel<<<dim3(Tn / 64, Bn * 4), 256>>>();
        split_aat<<<512, 256>>>();
        gemm_fc_tc<<<dim3(2, 32), 512, GSMEM>>>(l, fc_b + l * 256);
        add_ln_kernel<<<Mrows / 8, 256>>>(ln1_s + l * 256, ln1_b + l * 256);
        split_ax<<<512, 256>>>();
        gemm_w1_tc<<<dim3(8, 32), 512, GSMEM>>>(l, b1 + l * 1024);
        split_ah<<<1024, 256>>>();
        gemm_w2_tc<<<dim3(2, 32), 512, GSMEM>>>(l, b2 + l * 256);
        add_ln_kernel<<<Mrows / 8, 256>>>(ln2_s + l * 256, ln2_b + l * 256);
    }
    final_ln_kernel<<<Mrows / 8, 256>>>(lnf_s, lnf_b);
    split_ax<<<512, 256>>>();
    gemm_logits_tc<<<dim3(250, 32), 512, GSMEM>>>(out_b, logits);
}

// round 5
// speedup vs baseline: 1.9428x; 1.3636x over previous
#include <cuda_runtime.h>
#include <cuda_bf16.h>
#include <math.h>
#include <stdint.h>

// ---------------------------------------------------------------------------
// MiniGPT forward. B=2 T=2048 D=256 H=4 DK=64 DFF=1024 L=4 V=32000
// GEMMs: mma.sync bf16x3 compensated split. Producers write bf16 hi/lo
// directly (no separate split passes). Attention: fp32 flash, balanced pairs.
// ---------------------------------------------------------------------------

#define Tn    2048
#define Bn    2
#define Dn    256
#define Mrows 4096

// fp32 scratch
__device__ float g_x[Mrows * Dn];
__device__ float g_qkv[Mrows * 3 * Dn];
__device__ float g_tmp[Mrows * Dn];

// bf16 hi/lo activations (D-wide) and MLP hidden (DFF-wide)
__device__ __nv_bfloat16 g_acth[Mrows * Dn],  g_actl[Mrows * Dn];
__device__ __nv_bfloat16 g_hh[Mrows * 1024],  g_hl[Mrows * 1024];

// bf16 hi/lo weights
__device__ __nv_bfloat16 g_wqkv_h[4 * 768 * 256],  g_wqkv_l[4 * 768 * 256];
__device__ __nv_bfloat16 g_wfc_h [4 * 256 * 256],  g_wfc_l [4 * 256 * 256];
__device__ __nv_bfloat16 g_w1_h  [4 * 1024 * 256], g_w1_l  [4 * 1024 * 256];
__device__ __nv_bfloat16 g_w2_h  [4 * 256 * 1024], g_w2_l  [4 * 256 * 1024];
__device__ __nv_bfloat16 g_wout_h[32000 * 256],    g_wout_l[32000 * 256];

// ---------------------------------------------------------------------------
// PTX helpers
// ---------------------------------------------------------------------------
__device__ __forceinline__ uint32_t smem_to_u32(const void* p) {
    uint32_t a;
    asm("{ .reg .u64 t; cvta.to.shared.u64 t, %1; cvt.u32.u64 %0, t; }"
        : "=r"(a) : "l"(p));
    return a;
}
__device__ __forceinline__ void ldsm4(uint32_t* r, uint32_t addr) {
    asm volatile("ldmatrix.sync.aligned.m8n8.x4.shared.b16 {%0,%1,%2,%3}, [%4];"
                 : "=r"(r[0]), "=r"(r[1]), "=r"(r[2]), "=r"(r[3]) : "r"(addr));
}
__device__ __forceinline__ void mma16816(float* d, const uint32_t* a,
                                         uint32_t b0, uint32_t b1) {
    asm volatile(
        "mma.sync.aligned.m16n8k16.row.col.f32.bf16.bf16.f32 "
        "{%0,%1,%2,%3}, {%4,%5,%6,%7}, {%8,%9}, {%0,%1,%2,%3};"
        : "+f"(d[0]), "+f"(d[1]), "+f"(d[2]), "+f"(d[3])
        : "r"(a[0]), "r"(a[1]), "r"(a[2]), "r"(a[3]), "r"(b0), "r"(b1));
}
__device__ __forceinline__ float ex2f(float x) {
    float y;
    asm("ex2.approx.f32 %0, %1;" : "=f"(y) : "f"(x));
    return y;
}
#define CP_ASYNC16(dst, src) \
    asm volatile("cp.async.cg.shared.global [%0], [%1], 16;" \
                 :: "r"(dst), "l"(src) : "memory")
#define CP_COMMIT()  asm volatile("cp.async.commit_group;" ::: "memory")
#define CP_WAIT0()   asm volatile("cp.async.wait_group 0;" ::: "memory")

__device__ __forceinline__ void split1(float v, __nv_bfloat16& h, __nv_bfloat16& l) {
    h = __float2bfloat16(v);
    l = __float2bfloat16(v - __bfloat162float(h));
}

// ---------------------------------------------------------------------------
// Fused weight split: all 5 weight tensors in one kernel (grid-stride).
// ---------------------------------------------------------------------------
__global__ void split_weights(const float* __restrict__ qkv_w,
                              const float* __restrict__ fc_w,
                              const float* __restrict__ w1,
                              const float* __restrict__ w2,
                              const float* __restrict__ out_w)
{
    // float4 counts: 196608 | 65536 | 262144 | 262144 | 2048000
    const int c0 = 196608, c1 = c0 + 65536, c2 = c1 + 262144,
              c3 = c2 + 262144, c4 = c3 + 2048000;
    int stride = gridDim.x * blockDim.x;
    for (int idx = blockIdx.x * blockDim.x + threadIdx.x; idx < c4; idx += stride) {
        const float* src; __nv_bfloat16 *dh, *dl; int li;
        if (idx < c0)      { src = qkv_w; dh = g_wqkv_h; dl = g_wqkv_l; li = idx; }
        else if (idx < c1) { src = fc_w;  dh = g_wfc_h;  dl = g_wfc_l;  li = idx - c0; }
        else if (idx < c2) { src = w1;    dh = g_w1_h;   dl = g_w1_l;   li = idx - c1; }
        else if (idx < c3) { src = w2;    dh = g_w2_h;   dl = g_w2_l;   li = idx - c2; }
        else               { src = out_w; dh = g_wout_h; dl = g_wout_l; li = idx - c3; }
        float4 v = ((const float4*)src)[li];
        __nv_bfloat16 h0, h1, h2, h3, l0, l1, l2, l3;
        split1(v.x, h0, l0); split1(v.y, h1, l1);
        split1(v.z, h2, l2); split1(v.w, h3, l3);
        ((__nv_bfloat162*)dh)[li * 2 + 0] = __nv_bfloat162(h0, h1);
        ((__nv_bfloat162*)dh)[li * 2 + 1] = __nv_bfloat162(h2, h3);
        ((__nv_bfloat162*)dl)[li * 2 + 0] = __nv_bfloat162(l0, l1);
        ((__nv_bfloat162*)dl)[li * 2 + 1] = __nv_bfloat162(l2, l3);
    }
}

// ---------------------------------------------------------------------------
// mma.sync bf16x3 GEMM. TM in {128, 64}, TN = 128.
// TM=128: 512 thr, 16 warps (4x4), 128KB smem, stage = 64KB (4 x 16KB tiles)
// TM=64 : 256 thr,  8 warps (2x4),  96KB smem, stage = 48KB (8,8,16,16 KB)
// K staged 64 wide, double buffered, cp.async.
// WMODE: 0 = fp32 C + bias; 1 = fp32 C + bias + relu -> also unused;
//        epilogue selected by RELU/WSPLIT template flags.
// ---------------------------------------------------------------------------
#define GSMEM128 (2 * 65536)
#define GSMEM64  (2 * 49152)

template<int TM, int N, int K, int RELU, int WSPLIT>
__device__ __forceinline__ void gemm_body(
    const __nv_bfloat16* __restrict__ Ah, const __nv_bfloat16* __restrict__ Al,
    const __nv_bfloat16* __restrict__ Bh, const __nv_bfloat16* __restrict__ Bl,
    const float* __restrict__ bias, float* __restrict__ C,
    __nv_bfloat16* __restrict__ Ch, __nv_bfloat16* __restrict__ Cl)
{
    extern __shared__ char smem[];
    const uint32_t sb = smem_to_u32(smem);
    const int tid  = threadIdx.x;
    const int wid  = tid >> 5;
    const int lane = tid & 31;
    const int m0   = blockIdx.y * TM;
    const int n0   = blockIdx.x << 7;
    constexpr int NST   = K / 64;
    constexpr int STAGE = (TM == 128) ? 65536 : 49152;
    constexpr int AOFF  = (TM == 128) ? 16384 : 8192;   // Al offset
    constexpr int BOFF  = (TM == 128) ? 32768 : 16384;  // Bh offset
    constexpr int BSZ   = 16384;                        // per B tile
    const int wr = (TM == 128) ? (wid & 3) : (wid & 1);
    const int wc = (TM == 128) ? (wid >> 2) : (wid >> 1);

    float acc[2][4][4];
#pragma unroll
    for (int i = 0; i < 2; i++)
#pragma unroll
        for (int j = 0; j < 4; j++)
#pragma unroll
            for (int q = 0; q < 4; q++) acc[i][j][q] = 0.f;

    // ---- loader setup ------------------------------------------------------
    // TM=128: 512 threads, each owns one 128B row of one tile.
    // TM=64 : 256 threads, each owns 12 x 16B chunks: Ah r{q,q+32}, Al same,
    //         Bh r{q,q+32,q+64,q+96}, Bl same, fixed column (tid&7)*16 bytes.
    const __nv_bfloat16 *gp128 = nullptr;
    uint32_t dst128 = 0, sw128v = 0;
    const __nv_bfloat16 *pah = nullptr, *pal = nullptr, *pbh = nullptr, *pbl = nullptr;
    uint32_t dq = 0, swq = 0, cbyte = 0;
    if (TM == 128) {
        const int lr = tid & 127;
        const int lt = tid >> 7;
        gp128 = (lt == 0) ? Ah + (long)(m0 + lr) * K :
                (lt == 1) ? Al + (long)(m0 + lr) * K :
                (lt == 2) ? Bh + (long)(n0 + lr) * K :
                            Bl + (long)(n0 + lr) * K;
        dst128 = sb + lt * 16384 + lr * 128;
        sw128v = (uint32_t)((lr & 7) << 4);
    } else {
        const int q = tid >> 3;
        cbyte = (uint32_t)((tid & 7) << 4);
        swq   = cbyte ^ (uint32_t)((q & 7) << 4);
        dq    = (uint32_t)q;
        const int ce = (tid & 7) << 3;   // element offset
        pah = Ah + (long)(m0 + q) * K + ce;
        pal = Al + (long)(m0 + q) * K + ce;
        pbh = Bh + (long)(n0 + q) * K + ce;
        pbl = Bl + (long)(n0 + q) * K + ce;
    }

#define LOAD_STAGE(sbuf, koff)                                                  \
    do {                                                                        \
        if (TM == 128) {                                                        \
            const char* src = (const char*)(gp128 + (koff));                    \
            uint32_t db = dst128 + (sbuf) * (uint32_t)STAGE;                    \
            _Pragma("unroll")                                                   \
            for (int c = 0; c < 8; c++)                                         \
                CP_ASYNC16(db + (uint32_t)((c * 16) ^ sw128v), src + c * 16);   \
        } else {                                                                \
            uint32_t base = sb + (sbuf) * (uint32_t)STAGE;                      \
            _Pragma("unroll")                                                   \
            for (int u = 0; u < 2; u++) {                                       \
                uint32_t row = dq + u * 32;                                     \
                CP_ASYNC16(base + row * 128 + swq,                              \
                           (const char*)(pah + (long)u * 32 * K + (koff)));     \
                CP_ASYNC16(base + AOFF + row * 128 + swq,                       \
                           (const char*)(pal + (long)u * 32 * K + (koff)));     \
            }                                                                   \
            _Pragma("unroll")                                                   \
            for (int u = 0; u < 4; u++) {                                       \
                uint32_t row = dq + u * 32;                                     \
                CP_ASYNC16(base + BOFF + row * 128 + swq,                       \
                           (const char*)(pbh + (long)u * 32 * K + (koff)));     \
                CP_ASYNC16(base + BOFF + BSZ + row * 128 + swq,                 \
                           (const char*)(pbl + (long)u * 32 * K + (koff)));     \
            }                                                                   \
        }                                                                       \
        CP_COMMIT();                                                            \
    } while (0)

    LOAD_STAGE(0, 0);

    for (int s = 0; s < NST; s++) {
        CP_WAIT0();
        __syncthreads();
        if (s + 1 < NST) LOAD_STAGE((s + 1) & 1, (s + 1) * 64);
        const uint32_t bufb = sb + (uint32_t)((s & 1) * STAGE);

#pragma unroll
        for (int ko = 0; ko < 64; ko += 16) {
            uint32_t afr[2][2][4];
            uint32_t bfr[2][2][4];
            {
                const int rowb = wr * 32 + (lane & 15);
                const int cb   = ko * 2 + ((lane >> 4) << 4);
#pragma unroll
                for (int t = 0; t < 2; t++)
#pragma unroll
                    for (int mi = 0; mi < 2; mi++) {
                        int row = rowb + mi * 16;
                        uint32_t addr = bufb + (uint32_t)(t * AOFF) + row * 128
                                      + (uint32_t)(cb ^ ((row & 7) << 4));
                        ldsm4(afr[t][mi], addr);
                    }
            }
            {
                const int rowb = wc * 32 + (lane & 7) + ((lane >> 4) << 3);
                const int cb   = ko * 2 + (((lane >> 3) & 1) << 4);
#pragma unroll
                for (int t = 0; t < 2; t++)
#pragma unroll
                    for (int nj = 0; nj < 2; nj++) {
                        int row = rowb + nj * 16;
                        uint32_t addr = bufb + (uint32_t)BOFF + (uint32_t)(t * BSZ)
                                      + row * 128 + (uint32_t)(cb ^ ((row & 7) << 4));
                        ldsm4(bfr[t][nj], addr);
                    }
            }
#pragma unroll
            for (int mi = 0; mi < 2; mi++)
#pragma unroll
                for (int nj = 0; nj < 2; nj++)
#pragma unroll
                    for (int hh = 0; hh < 2; hh++) {
                        const int nc = nj * 2 + hh;
                        const uint32_t bh0 = bfr[0][nj][hh * 2];
                        const uint32_t bh1 = bfr[0][nj][hh * 2 + 1];
                        const uint32_t bl0 = bfr[1][nj][hh * 2];
                        const uint32_t bl1 = bfr[1][nj][hh * 2 + 1];
                        mma16816(acc[mi][nc], afr[0][mi], bh0, bh1);
                        mma16816(acc[mi][nc], afr[0][mi], bl0, bl1);
                        mma16816(acc[mi][nc], afr[1][mi], bh0, bh1);
                    }
        }
        __syncthreads();
    }
#undef LOAD_STAGE

    // ---- epilogue ----------------------------------------------------------
#pragma unroll
    for (int mi = 0; mi < 2; mi++)
#pragma unroll
        for (int nc = 0; nc < 4; nc++) {
            int row = m0 + wr * 32 + mi * 16 + (lane >> 2);
            int col = n0 + wc * 32 + nc * 8 + (lane & 3) * 2;
            float b0v = bias[col], b1v = bias[col + 1];
            float v0 = acc[mi][nc][0] + b0v;
            float v1 = acc[mi][nc][1] + b1v;
            float v2 = acc[mi][nc][2] + b0v;
            float v3 = acc[mi][nc][3] + b1v;
            if (RELU) {
                v0 = fmaxf(v0, 0.f); v1 = fmaxf(v1, 0.f);
                v2 = fmaxf(v2, 0.f); v3 = fmaxf(v3, 0.f);
            }
            if (WSPLIT) {
                __nv_bfloat16 h0, h1, h2, h3, l0, l1, l2, l3;
                split1(v0, h0, l0); split1(v1, h1, l1);
                split1(v2, h2, l2); split1(v3, h3, l3);
                *(__nv_bfloat162*)(Ch + (long)row * N + col)       = __nv_bfloat162(h0, h1);
                *(__nv_bfloat162*)(Ch + (long)(row + 8) * N + col) = __nv_bfloat162(h2, h3);
                *(__nv_bfloat162*)(Cl + (long)row * N + col)       = __nv_bfloat162(l0, l1);
                *(__nv_bfloat162*)(Cl + (long)(row + 8) * N + col) = __nv_bfloat162(l2, l3);
            } else {
                *(float2*)(C + (long)row * N + col)       = make_float2(v0, v1);
                *(float2*)(C + (long)(row + 8) * N + col) = make_float2(v2, v3);
            }
        }
}

__global__ __launch_bounds__(256) void gemm_qkv_tc(int l, const float* bias)
{ gemm_body<64, 768, 256, 0, 0>(g_acth, g_actl, g_wqkv_h + l*196608, g_wqkv_l + l*196608,
                                bias, g_qkv, nullptr, nullptr); }
__global__ __launch_bounds__(256) void gemm_fc_tc(int l, const float* bias)
{ gemm_body<64, 256, 256, 0, 0>(g_acth, g_actl, g_wfc_h + l*65536, g_wfc_l + l*65536,
                                bias, g_tmp, nullptr, nullptr); }
__global__ __launch_bounds__(512) void gemm_w1_tc(int l, const float* bias)
{ gemm_body<128, 1024, 256, 1, 1>(g_acth, g_actl, g_w1_h + l*262144, g_w1_l + l*262144,
                                  bias, nullptr, g_hh, g_hl); }
__global__ __launch_bounds__(256) void gemm_w2_tc(int l, const float* bias)
{ gemm_body<64, 256, 1024, 0, 0>(g_hh, g_hl, g_w2_h + l*262144, g_w2_l + l*262144,
                                 bias, g_tmp, nullptr, nullptr); }
__global__ __launch_bounds__(512) void gemm_logits_tc(const float* bias, float* out)
{ gemm_body<128, 32000, 256, 0, 0>(g_acth, g_actl, g_wout_h, g_wout_l,
                                   bias, out, nullptr, nullptr); }

// ---------------------------------------------------------------------------
// Embedding + positional encoding (writes x and hi/lo)
// ---------------------------------------------------------------------------
__global__ void embed_pos_kernel(const int* __restrict__ tok,
                                 const float* __restrict__ emb)
{
    int row = blockIdx.x;
    int d   = threadIdx.x;
    int t   = row & (Tn - 1);
    int token = tok[row];
    double div = exp(-(double)(d & ~1) * (9.210340371976184 / 256.0));
    double ang = (double)t * div;
    float  pe  = (d & 1) ? (float)cos(ang) : (float)sin(ang);
    float v = emb[token * Dn + d] + pe;
    g_x[row * Dn + d] = v;
    __nv_bfloat16 h, l;
    split1(v, h, l);
    g_acth[row * Dn + d] = h;
    g_actl[row * Dn + d] = l;
}

// ---------------------------------------------------------------------------
// Flash attention (causal), fp32. Paired q-tiles for balance: block bx
// handles qt = bx and qt = 31-bx (33 tile-iters each block). log2 domain
// softmax with ex2.approx. Output -> bf16 hi/lo (fc GEMM A operand).
// ---------------------------------------------------------------------------
#define SWZ(r, c) ((c) ^ (((r) & 15) << 2))
#define QSCALE 0.18033688f    /* 0.125 * log2(e) */

__global__ __launch_bounds__(256) void attn_kernel()
{
    __shared__ float Qs[4096];
    __shared__ float KPs[4096];
    __shared__ float Vs[4096];

    const int tid = threadIdx.x;
    const int tx  = tid & 15;
    const int ty  = tid >> 4;
    const int b   = blockIdx.y >> 2;
    const int h   = blockIdx.y & 3;
    const float* qbase = g_qkv + (long)b * Tn * 768 + h * 64;

    for (int pass = 0; pass < 2; pass++) {
        const int qt = pass ? (31 - (int)blockIdx.x) : (int)blockIdx.x;
        const int q0 = qt << 6;

#pragma unroll
        for (int rep = 0; rep < 4; rep++) {
            int idx = tid + rep * 256;
            int rr  = idx >> 4;
            int d4  = (idx & 15) << 2;
            float4 q4 = *(const float4*)(qbase + (long)(q0 + rr) * 768 + d4);
            Qs[(d4 + 0) * 64 + SWZ(d4 + 0, rr)] = q4.x * QSCALE;
            Qs[(d4 + 1) * 64 + SWZ(d4 + 1, rr)] = q4.y * QSCALE;
            Qs[(d4 + 2) * 64 + SWZ(d4 + 2, rr)] = q4.z * QSCALE;
            Qs[(d4 + 3) * 64 + SWZ(d4 + 3, rr)] = q4.w * QSCALE;
        }

        float m_i[4], l_i[4], o[4][4];
#pragma unroll
        for (int i = 0; i < 4; i++) {
            m_i[i] = -1e30f; l_i[i] = 0.f;
#pragma unroll
            for (int j = 0; j < 4; j++) o[i][j] = 0.f;
        }

        for (int kt = 0; kt <= qt; kt++) {
            __syncthreads();
            const int k0 = kt << 6;
#pragma unroll
            for (int rep = 0; rep < 4; rep++) {
                int idx = tid + rep * 256;
                int rr  = idx >> 4;
                int d4  = (idx & 15) << 2;
                const float* kb = qbase + (long)(k0 + rr) * 768;
                float4 k4 = *(const float4*)(kb + 256 + d4);
                KPs[(d4 + 0) * 64 + SWZ(d4 + 0, rr)] = k4.x;
                KPs[(d4 + 1) * 64 + SWZ(d4 + 1, rr)] = k4.y;
                KPs[(d4 + 2) * 64 + SWZ(d4 + 2, rr)] = k4.z;
                KPs[(d4 + 3) * 64 + SWZ(d4 + 3, rr)] = k4.w;
                float4 v4 = *(const float4*)(kb + 512 + d4);
                *(float4*)(Vs + rr * 64 + d4) = v4;
            }
            __syncthreads();

            float s[4][4];
#pragma unroll
            for (int i = 0; i < 4; i++)
#pragma unroll
                for (int j = 0; j < 4; j++) s[i][j] = 0.f;
#pragma unroll 8
            for (int d = 0; d < 64; d++) {
                float4 qa = *(const float4*)&Qs[d * 64 + SWZ(d, ty * 4)];
                float4 ka = *(const float4*)&KPs[d * 64 + SWZ(d, tx * 4)];
                float qv[4] = {qa.x, qa.y, qa.z, qa.w};
                float kv[4] = {ka.x, ka.y, ka.z, ka.w};
#pragma unroll
                for (int i = 0; i < 4; i++)
#pragma unroll
                    for (int j = 0; j < 4; j++)
                        s[i][j] = fmaf(qv[i], kv[j], s[i][j]);
            }

            if (kt == qt) {
#pragma unroll
                for (int i = 0; i < 4; i++)
#pragma unroll
                    for (int j = 0; j < 4; j++)
                        if (tx * 4 + j > ty * 4 + i) s[i][j] = -1e30f;
            }

#pragma unroll
            for (int i = 0; i < 4; i++) {
                float mx = fmaxf(fmaxf(s[i][0], s[i][1]), fmaxf(s[i][2], s[i][3]));
#pragma unroll
                for (int ofs = 8; ofs; ofs >>= 1)
                    mx = fmaxf(mx, __shfl_xor_sync(0xffffffffu, mx, ofs, 16));
                float mn   = fmaxf(m_i[i], mx);
                float corr = ex2f(m_i[i] - mn);
                float rs = 0.f;
#pragma unroll
                for (int j = 0; j < 4; j++) {
                    s[i][j] = ex2f(s[i][j] - mn);
                    rs += s[i][j];
                }
#pragma unroll
                for (int ofs = 8; ofs; ofs >>= 1)
                    rs += __shfl_xor_sync(0xffffffffu, rs, ofs, 16);
                l_i[i] = l_i[i] * corr + rs;
                m_i[i] = mn;
#pragma unroll
                for (int j = 0; j < 4; j++) o[i][j] *= corr;
            }

            __syncthreads();
#pragma unroll
            for (int i = 0; i < 4; i++)
#pragma unroll
                for (int j = 0; j < 4; j++) {
                    int n = tx * 4 + j;
                    KPs[n * 64 + SWZ(n, ty * 4 + i)] = s[i][j];
                }
            __syncthreads();

#pragma unroll 8
            for (int n = 0; n < 64; n++) {
                float4 p4 = *(const float4*)&KPs[n * 64 + SWZ(n, ty * 4)];
                float4 v4 = *(const float4*)&Vs[n * 64 + tx * 4];
                float pv[4] = {p4.x, p4.y, p4.z, p4.w};
                float vv[4] = {v4.x, v4.y, v4.z, v4.w};
#pragma unroll
                for (int i = 0; i < 4; i++)
#pragma unroll
                    for (int j = 0; j < 4; j++)
                        o[i][j] = fmaf(pv[i], vv[j], o[i][j]);
            }
        }

        // write O as bf16 hi/lo (A operand of fc GEMM)
#pragma unroll
        for (int i = 0; i < 4; i++) {
            float inv = 1.f / l_i[i];
            long base = (long)(b * Tn + q0 + ty * 4 + i) * Dn + h * 64 + tx * 4;
            __nv_bfloat16 h0, h1, h2, h3, l0, l1, l2, l3;
            split1(o[i][0] * inv, h0, l0); split1(o[i][1] * inv, h1, l1);
            split1(o[i][2] * inv, h2, l2); split1(o[i][3] * inv, h3, l3);
            *(__nv_bfloat162*)(g_acth + base)     = __nv_bfloat162(h0, h1);
            *(__nv_bfloat162*)(g_acth + base + 2) = __nv_bfloat162(h2, h3);
            *(__nv_bfloat162*)(g_actl + base)     = __nv_bfloat162(l0, l1);
            *(__nv_bfloat162*)(g_actl + base + 2) = __nv_bfloat162(l2, l3);
        }
        __syncthreads();
    }
}

// ---------------------------------------------------------------------------
// LayerNorm: x = LN(x [+ g_tmp]) * sc + bi ; writes x fp32 AND hi/lo bf16.
// ---------------------------------------------------------------------------
template<int ADD>
__device__ __forceinline__ void ln_body(const float* __restrict__ sc,
                                        const float* __restrict__ bi)
{
    int row  = blockIdx.x * 8 + (threadIdx.x >> 5);
    int lane = threadIdx.x & 31;
    const float* pa = g_x + (long)row * Dn + lane * 8;
    float v[8];
    {
        float4 v0 = *(const float4*)pa;
        float4 v1 = *(const float4*)(pa + 4);
        v[0] = v0.x; v[1] = v0.y; v[2] = v0.z; v[3] = v0.w;
        v[4] = v1.x; v[5] = v1.y; v[6] = v1.z; v[7] = v1.w;
    }
    if (ADD) {
        const float* pr = g_tmp + (long)row * Dn + lane * 8;
        float4 r0 = *(const float4*)pr;
        float4 r1 = *(const float4*)(pr + 4);
        v[0] += r0.x; v[1] += r0.y; v[2] += r0.z; v[3] += r0.w;
        v[4] += r1.x; v[5] += r1.y; v[6] += r1.z; v[7] += r1.w;
    }
    float s = 0.f;
#pragma unroll
    for (int k = 0; k < 8; k++) s += v[k];
#pragma unroll
    for (int ofs = 16; ofs; ofs >>= 1) s += __shfl_xor_sync(0xffffffffu, s, ofs);
    float mu = s * (1.f / 256.f);
    float var = 0.f;
#pragma unroll
    for (int k = 0; k < 8; k++) { float d = v[k] - mu; var = fmaf(d, d, var); }
#pragma unroll
    for (int ofs = 16; ofs; ofs >>= 1) var += __shfl_xor_sync(0xffffffffu, var, ofs);
    float rstd = rsqrtf(var * (1.f / 256.f) + 1e-5f);

    float4 s0 = *(const float4*)(sc + lane * 8);
    float4 s1 = *(const float4*)(sc + lane * 8 + 4);
    float4 b0 = *(const float4*)(bi + lane * 8);
    float4 b1 = *(const float4*)(bi + lane * 8 + 4);
    float scv[8] = {s0.x, s0.y, s0.z, s0.w, s1.x, s1.y, s1.z, s1.w};
    float biv[8] = {b0.x, b0.y, b0.z, b0.w, b1.x, b1.y, b1.z, b1.w};
    float o[8];
    __nv_bfloat16 oh[8], ol[8];
#pragma unroll
    for (int k = 0; k < 8; k++) {
        o[k] = fmaf((v[k] - mu) * rstd, scv[k], biv[k]);
        split1(o[k], oh[k], ol[k]);
    }
    long base = (long)row * Dn + lane * 8;
    *(float4*)(g_x + base)     = make_float4(o[0], o[1], o[2], o[3]);
    *(float4*)(g_x + base + 4) = make_float4(o[4], o[5], o[6], o[7]);
#pragma unroll
    for (int k = 0; k < 4; k++) {
        ((__nv_bfloat162*)(g_acth + base))[k] = __nv_bfloat162(oh[2*k], oh[2*k+1]);
        ((__nv_bfloat162*)(g_actl + base))[k] = __nv_bfloat162(ol[2*k], ol[2*k+1]);
    }
}
__global__ void add_ln_kernel(const float* sc, const float* bi) { ln_body<1>(sc, bi); }
__global__ void final_ln_kernel(const float* sc, const float* bi) { ln_body<0>(sc, bi); }

// ---------------------------------------------------------------------------
// Orchestration
// ---------------------------------------------------------------------------
extern "C" void kernel_launch(void* const* d_in, const int* in_sizes, int n_in,
                              void* d_out, int out_size)
{
    const int*   tokens = (const int*)d_in[0];
    const float* embedw = (const float*)d_in[1];
    const float* qkv_w  = (const float*)d_in[2];
    const float* qkv_b  = (const float*)d_in[3];
    const float* fc_w   = (const float*)d_in[4];
    const float* fc_b   = (const float*)d_in[5];
    const float* ln1_s  = (const float*)d_in[6];
    const float* ln1_b  = (const float*)d_in[7];
    const float* w1     = (const float*)d_in[8];
    const float* b1     = (const float*)d_in[9];
    const float* w2     = (const float*)d_in[10];
    const float* b2     = (const float*)d_in[11];
    const float* ln2_s  = (const float*)d_in[12];
    const float* ln2_b  = (const float*)d_in[13];
    const float* lnf_s  = (const float*)d_in[14];
    const float* lnf_b  = (const float*)d_in[15];
    const float* out_w  = (const float*)d_in[16];
    const float* out_b  = (const float*)d_in[17];
    float* logits = (float*)d_out;

    cudaFuncSetAttribute((const void*)gemm_qkv_tc,
        cudaFuncAttributeMaxDynamicSharedMemorySize, GSMEM64);
    cudaFuncSetAttribute((const void*)gemm_fc_tc,
        cudaFuncAttributeMaxDynamicSharedMemorySize, GSMEM64);
    cudaFuncSetAttribute((const void*)gemm_w1_tc,
        cudaFuncAttributeMaxDynamicSharedMemorySize, GSMEM128);
    cudaFuncSetAttribute((const void*)gemm_w2_tc,
        cudaFuncAttributeMaxDynamicSharedMemorySize, GSMEM64);
    cudaFuncSetAttribute((const void*)gemm_logits_tc,
        cudaFuncAttributeMaxDynamicSharedMemorySize, GSMEM128);

    split_weights<<<2048, 256>>>(qkv_w, fc_w, w1, w2, out_w);
    embed_pos_kernel<<<Mrows, Dn>>>(tokens, embedw);

    for (int l = 0; l < 4; l++) {
        gemm_qkv_tc<<<dim3(6, 64), 256, GSMEM64>>>(l, qkv_b + l * 768);
        attn_kernel<<<dim3(16, Bn * 4), 256>>>();
        gemm_fc_tc<<<dim3(2, 64), 256, GSMEM64>>>(l, fc_b + l * 256);
        add_ln_kernel<<<Mrows / 8, 256>>>(ln1_s + l * 256, ln1_b + l * 256);
        gemm_w1_tc<<<dim3(8, 32), 512, GSMEM128>>>(l, b1 + l * 1024);
        gemm_w2_tc<<<dim3(2, 64), 256, GSMEM64>>>(l, b2 + l * 256);
        add_ln_kernel<<<Mrows / 8, 256>>>(ln2_s + l * 256, ln2_b + l * 256);
    }
    final_ln_kernel<<<Mrows / 8, 256>>>(lnf_s, lnf_b);
    gemm_logits_tc<<<dim3(250, 32), 512, GSMEM128>>>(out_b, logits);
}